// round 3
// baseline (speedup 1.0000x reference)
#include <cuda_runtime.h>
#include <cuda_bf16.h>
#include <cstdint>

// ---------------- problem-size scratch (static device globals; no allocs) ---
#define NMAX 100096
#define EMAX 1600256
#define ENMAX (NMAX + EMAX)

__device__ int    g_not64;               // 1 if edge_index is int32
__device__ int    g_deg[NMAX];
__device__ int    g_rp[NMAX + 1];
__device__ int    g_cur[NMAX];
__device__ int    g_bsum[128];
__device__ int    g_ss[ENMAX];           // src indices sorted by dst (CSR payload)
__device__ float2 g_h1[NMAX * 32];       // layer1 features, interleaved (c, c+32)
__device__ float  g_g1[NMAX * 64];       // layer1 output (post relu) = layer2 input
__device__ float2 g_h2[NMAX * 32];       // layer2 features, interleaved
__device__ float  g_g2[NMAX * 64];       // layer2 output
__device__ float  g_as1[NMAX], g_ad1[NMAX];
__device__ float  g_as2[NMAX], g_ad2[NMAX];

// ---------------- init ------------------------------------------------------
__global__ void k_zero(float* __restrict__ out, int n) {
    int i = blockIdx.x * blockDim.x + threadIdx.x;
    if (i < n) g_deg[i] = 0;
    if (i < 64) out[i] = 0.f;
    if (i == 0) g_not64 = 0;
}

// ---------------- edge-index dtype detection --------------------------------
// int64 indices < 100000 have zero high words; int32 data read as qwords has
// nonzero high words w.p. ~1 per 1e5 elements -> checking 2048 qwords decides.
__global__ void k_detect(const long long* __restrict__ ei, int nq) {
    int i = blockIdx.x * blockDim.x + threadIdx.x;
    if (i < nq && ((unsigned long long)ei[i] >> 32) != 0ull) atomicOr(&g_not64, 1);
}

__device__ __forceinline__ int load_idx(const void* ei, long long pos) {
    if (g_not64) return ((const int*)ei)[pos];
    return (int)((const long long*)ei)[pos];
}

__device__ __forceinline__ int clampi(int v, int n) {
    v = v < 0 ? 0 : v;
    return v >= n ? n - 1 : v;
}

// ---------------- degree histogram (incl. self loops) -----------------------
__global__ void k_hist(const void* __restrict__ ei, int E, int EN, int n) {
    int i = blockIdx.x * blockDim.x + threadIdx.x;
    if (i >= EN) return;
    int d = (i < E) ? clampi(load_idx(ei, (long long)E + i), n) : (i - E);
    atomicAdd(&g_deg[d], 1);
}

// ---------------- prefix scan (3 kernels) -----------------------------------
__global__ void k_scan_block(int n) {
    __shared__ int s[1024];
    int i = blockIdx.x * 1024 + threadIdx.x;
    int v = (i < n) ? g_deg[i] : 0;
    s[threadIdx.x] = v;
    __syncthreads();
#pragma unroll
    for (int o = 1; o < 1024; o <<= 1) {
        int t = (threadIdx.x >= (unsigned)o) ? s[threadIdx.x - o] : 0;
        __syncthreads();
        s[threadIdx.x] += t;
        __syncthreads();
    }
    if (i < n) g_rp[i] = s[threadIdx.x] - v;          // exclusive within block
    if (threadIdx.x == 1023) g_bsum[blockIdx.x] = s[1023];
}

__global__ void k_scan_top(int nb) {
    if (threadIdx.x == 0 && blockIdx.x == 0) {
        int acc = 0;
        for (int i = 0; i < nb; i++) { int v = g_bsum[i]; g_bsum[i] = acc; acc += v; }
    }
}

__global__ void k_scan_add(int n, int total) {
    int i = blockIdx.x * blockDim.x + threadIdx.x;
    if (i < n) {
        int v = g_rp[i] + g_bsum[i >> 10];
        g_rp[i] = v;
        g_cur[i] = v;
    }
    if (i == 0) g_rp[n] = total;
}

// ---------------- scatter edges into CSR order ------------------------------
__global__ void k_scatter(const void* __restrict__ ei, int E, int EN, int n) {
    int i = blockIdx.x * blockDim.x + threadIdx.x;
    if (i >= EN) return;
    int s, d;
    if (i < E) {
        s = clampi(load_idx(ei, i), n);
        d = clampi(load_idx(ei, (long long)E + i), n);
    } else { s = i - E; d = s; }
    int pos = atomicAdd(&g_cur[d], 1);
    if (pos >= 0 && pos < ENMAX) g_ss[pos] = s;
}

// ---------------- GEMM + attention scalars ----------------------------------
// h = X @ W (Fout = 64), a_src = h . att_s, a_dst = h . att_d
// warp handles 4 node rows; W packed float2 (c, c+32) in smem.
// H written interleaved: H[node*32 + lane] = (h[lane], h[lane+32])
template <int FIN>
__global__ void __launch_bounds__(128)
k_gemm(const float* __restrict__ X, const float* __restrict__ Wg,
       const float* __restrict__ att_s, const float* __restrict__ att_d,
       float2* __restrict__ H, float* __restrict__ AS, float* __restrict__ AD,
       int n) {
    __shared__ float2 Wp[FIN * 32];
    __shared__ float atts[64], attd[64];
    __shared__ __align__(16) float xs[4][4][FIN];

    int tid = threadIdx.x;
    for (int i = tid; i < FIN * 32; i += 128) {
        int k = i >> 5, c = i & 31;
        Wp[i] = make_float2(Wg[k * 64 + c], Wg[k * 64 + c + 32]);
    }
    if (tid < 64) { atts[tid] = att_s[tid]; attd[tid] = att_d[tid]; }
    __syncthreads();

    int warp = tid >> 5, lane = tid & 31;
    int gw = blockIdx.x * 4 + warp;
    int totw = gridDim.x * 4;

    for (int base = gw * 4; base < n; base += totw * 4) {
        int nrows = n - base;
        if (nrows > 4) nrows = 4;
        for (int r = 0; r < nrows; r++) {
            const float* xp = X + (size_t)(base + r) * FIN;
#pragma unroll
            for (int k = lane; k < FIN; k += 32) xs[warp][r][k] = xp[k];
        }
        __syncwarp();

        float acc[4][2];
#pragma unroll
        for (int r = 0; r < 4; r++) { acc[r][0] = 0.f; acc[r][1] = 0.f; }

#pragma unroll 8
        for (int k4 = 0; k4 < FIN; k4 += 4) {
            float4 xv[4];
#pragma unroll
            for (int r = 0; r < 4; r++)
                xv[r] = *(const float4*)&xs[warp][r][k4];
#pragma unroll
            for (int kk = 0; kk < 4; kk++) {
                float2 w = Wp[(k4 + kk) * 32 + lane];
#pragma unroll
                for (int r = 0; r < 4; r++) {
                    float xr = (kk == 0) ? xv[r].x : (kk == 1) ? xv[r].y
                             : (kk == 2) ? xv[r].z : xv[r].w;
                    acc[r][0] += xr * w.x;
                    acc[r][1] += xr * w.y;
                }
            }
        }

        for (int r = 0; r < nrows; r++) {
            float v0 = acc[r][0], v1 = acc[r][1];
            H[(size_t)(base + r) * 32 + lane] = make_float2(v0, v1);
            float ps = v0 * atts[lane] + v1 * atts[lane + 32];
            float pd = v0 * attd[lane] + v1 * attd[lane + 32];
#pragma unroll
            for (int ofs = 16; ofs; ofs >>= 1) {
                ps += __shfl_xor_sync(0xffffffffu, ps, ofs);
                pd += __shfl_xor_sync(0xffffffffu, pd, ofs);
            }
            if (lane == 0) { AS[base + r] = ps; AD[base + r] = pd; }
        }
        __syncwarp();
    }
}

// ---------------- fused softmax-attention aggregation (warp per node) -------
// out[d] = (sum_i exp(lrelu(a_src[s_i]+a_dst[d])) * h[s_i]) / (sum_i exp(...)) + b
__global__ void __launch_bounds__(256)
k_agg(const float2* __restrict__ H, const float* __restrict__ AS,
      const float* __restrict__ AD, const float* __restrict__ bias,
      float* __restrict__ OUT, int n, int do_relu) {
    int gw = (blockIdx.x * blockDim.x + threadIdx.x) >> 5;
    int lane = threadIdx.x & 31;
    if (gw >= n) return;

    float adv = AD[gw];
    int beg = g_rp[gw], end = g_rp[gw + 1];

    float den = 0.f, acc0 = 0.f, acc1 = 0.f;
    int j = beg;
    int sNext = (j < end) ? g_ss[j] : 0;
    for (; j < end; ) {
        int s = sNext;
        j++;
        if (j < end) sNext = g_ss[j];         // prefetch next src index
        float e = AS[s] + adv;
        e = (e > 0.f) ? e : 0.2f * e;         // leaky_relu, slope 0.2
        float w = __expf(e);
        float2 hv = H[(size_t)s * 32 + lane];
        den += w;
        acc0 += w * hv.x;
        acc1 += w * hv.y;
    }
    float inv = 1.f / (den + 1e-16f);
    float v0 = fmaf(acc0, inv, bias[lane]);
    float v1 = fmaf(acc1, inv, bias[lane + 32]);
    if (do_relu) { v0 = fmaxf(v0, 0.f); v1 = fmaxf(v1, 0.f); }
    size_t o = (size_t)gw * 64;
    OUT[o + lane] = v0;
    OUT[o + 32 + lane] = v1;
}

// ---------------- global mean pool ------------------------------------------
__global__ void k_pool(const float* __restrict__ G, float* __restrict__ out, int n) {
    __shared__ float sm[256];
    int col = threadIdx.x & 63;
    int rg = threadIdx.x >> 6;   // 0..3
    float acc = 0.f;
    for (int r = blockIdx.x * 4 + rg; r < n; r += gridDim.x * 4)
        acc += G[(size_t)r * 64 + col];
    sm[threadIdx.x] = acc;
    __syncthreads();
    if (rg == 0) {
        float v = sm[col] + sm[64 + col] + sm[128 + col] + sm[192 + col];
        atomicAdd(&out[col], v * (1.0f / (float)n));
    }
}

// ---------------- launch ----------------------------------------------------
extern "C" void kernel_launch(void* const* d_in, const int* in_sizes, int n_in,
                              void* d_out, int out_size) {
    const float* x   = (const float*)d_in[0];
    const void*  ei  = d_in[1];   // edge_index, dtype detected on device
    // d_in[2] = edge_attr (unused: edge_dim=None in reference)
    const float* W1  = (const float*)d_in[3];
    const float* as1 = (const float*)d_in[4];
    const float* ad1 = (const float*)d_in[5];
    const float* b1  = (const float*)d_in[6];
    const float* W2  = (const float*)d_in[7];
    const float* as2 = (const float*)d_in[8];
    const float* ad2 = (const float*)d_in[9];
    const float* b2  = (const float*)d_in[10];
    float* out = (float*)d_out;

    int n  = in_sizes[0] / 128;   // N nodes
    int E  = in_sizes[1] / 2;     // edges
    int EN = E + n;               // edges + self loops

    // --- detect edge_index dtype, build CSR by destination ---
    k_zero<<<(n + 255) / 256, 256>>>(out, n);
    int nq = E < 2048 ? E : 2048;
    k_detect<<<(nq + 255) / 256, 256>>>((const long long*)ei, nq);
    k_hist<<<(EN + 255) / 256, 256>>>(ei, E, EN, n);
    int nb = (n + 1023) / 1024;
    k_scan_block<<<nb, 1024>>>(n);
    k_scan_top<<<1, 32>>>(nb);
    k_scan_add<<<(n + 255) / 256, 256>>>(n, EN);
    k_scatter<<<(EN + 255) / 256, 256>>>(ei, E, EN, n);

    // --- layer 1: GEMM(128->64) + attention aggregation + relu ---
    k_gemm<128><<<740, 128>>>(x, W1, as1, ad1, g_h1, g_as1, g_ad1, n);
    k_agg<<<(n + 7) / 8, 256>>>(g_h1, g_as1, g_ad1, b1, g_g1, n, 1);

    // --- layer 2: GEMM(64->64) + attention aggregation ---
    k_gemm<64><<<740, 128>>>(g_g1, W2, as2, ad2, g_h2, g_as2, g_ad2, n);
    k_agg<<<(n + 7) / 8, 256>>>(g_h2, g_as2, g_ad2, b2, g_g2, n, 0);

    // --- global mean pool ---
    k_pool<<<256, 256>>>(g_g2, out, n);
}